// round 14
// baseline (speedup 1.0000x reference)
#include <cuda_runtime.h>

#define BB 4
#define SS 12
#define NN 512
#define CIN 3
#define COUT 3
#define HID 64
#define HEADS 8
#define DH 8
#define LAYERS 2
#define NE 8192
#define BSN (BB*SS*NN)

// ---------------- f32x2 packed-FMA helpers (sm_100+: ptxas won't auto-fuse) --
__device__ __forceinline__ unsigned long long pack2(float lo, float hi) {
    unsigned long long r;
    asm("mov.b64 %0, {%1, %2};" : "=l"(r) : "f"(lo), "f"(hi));
    return r;
}
__device__ __forceinline__ void unpack2(unsigned long long v, float& lo, float& hi) {
    asm("mov.b64 {%0, %1}, %2;" : "=f"(lo), "=f"(hi) : "l"(v));
}
__device__ __forceinline__ unsigned long long fma2(unsigned long long a,
                                                   unsigned long long b,
                                                   unsigned long long c) {
    unsigned long long d;
    asm("fma.rn.f32x2 %0, %1, %2, %3;" : "=l"(d) : "l"(a), "l"(b), "l"(c));
    return d;
}
__device__ __forceinline__ unsigned long long mul2(unsigned long long a,
                                                   unsigned long long b) {
    unsigned long long d;
    asm("mul.rn.f32x2 %0, %1, %2;" : "=l"(d) : "l"(a), "l"(b));
    return d;
}
__device__ __forceinline__ unsigned long long add2(unsigned long long a,
                                                   unsigned long long b) {
    unsigned long long d;
    asm("add.rn.f32x2 %0, %1, %2;" : "=l"(d) : "l"(a), "l"(b));
    return d;
}

// ---------------- scratch (device globals: no allocs allowed) ----------------
__device__ float g_h[BSN*HID];
__device__ float g_q[BSN*HID];
__device__ float g_k[BSN*HID];
__device__ float g_v[BSN*HID];
__device__ unsigned g_mask[NN*16];   // 512 rows x 512-bit mask

// ---------------- mask build ----------------
__global__ void zero_mask_kernel() {
    int i = blockIdx.x*256 + threadIdx.x;
    if (i < NN*16) g_mask[i] = 0u;
}

__global__ void scatter_mask_kernel(const int* __restrict__ ei) {
    int e = blockIdx.x*256 + threadIdx.x;
    if (e < NE) {
        int r = ei[e];
        int c = ei[NE + e];
        atomicOr(&g_mask[r*16 + (c >> 5)], 1u << (c & 31));
    }
}

// ---------------- input projection: h = x @ Win^T + b_in ----------------
__global__ void input_proj_kernel(const float* __restrict__ x,
                                  const float* __restrict__ Win,
                                  const float* __restrict__ bin) {
    int i = blockIdx.x*256 + threadIdx.x;
    if (i >= BSN*HID) return;
    int row = i >> 6, c = i & 63;
    const float* xr = x + row*CIN;
    float a = bin[c];
    a += xr[0]*Win[c*CIN+0];
    a += xr[1]*Win[c*CIN+1];
    a += xr[2]*Win[c*CIN+2];
    g_h[i] = a;
}

// ---------------- fused QKV projection (reads g_h, writes g_q/g_k/g_v) -------
// Block: 64 rows. Thread: 4 rows x 4 cols x 3 matrices, f32x2 accumulators.
__global__ __launch_bounds__(256, 3) void qkv_proj_kernel(
        const float* __restrict__ Wq, const float* __restrict__ bq,
        const float* __restrict__ Wk, const float* __restrict__ bk,
        const float* __restrict__ Wv, const float* __restrict__ bv) {
    __shared__ float Ws[3][HID*HID];      // 48 KB, stored transposed [k][c]
    int tid = threadIdx.x;
    for (int i = tid; i < HID*HID; i += 256) {
        int c = i >> 6, k = i & 63;
        Ws[0][k*HID + c] = Wq[i];
        Ws[1][k*HID + c] = Wk[i];
        Ws[2][k*HID + c] = Wv[i];
    }
    __syncthreads();

    int cg = (tid & 15) * 4;
    int rbase = blockIdx.x*64 + (tid >> 4)*4;

    // acc[mat][row][colpair] as f32x2
    unsigned long long acc[3][4][2];
    #pragma unroll
    for (int m = 0; m < 3; m++) {
        const float* bias = (m == 0) ? bq : (m == 1) ? bk : bv;
        unsigned long long b01 = pack2(bias[cg+0], bias[cg+1]);
        unsigned long long b23 = pack2(bias[cg+2], bias[cg+3]);
        #pragma unroll
        for (int r = 0; r < 4; r++) { acc[m][r][0] = b01; acc[m][r][1] = b23; }
    }

    const float4* hp0 = (const float4*)(g_h + (rbase+0)*HID);
    const float4* hp1 = (const float4*)(g_h + (rbase+1)*HID);
    const float4* hp2 = (const float4*)(g_h + (rbase+2)*HID);
    const float4* hp3 = (const float4*)(g_h + (rbase+3)*HID);

    #pragma unroll 4
    for (int k4 = 0; k4 < 16; k4++) {
        float4 hv[4];
        hv[0] = hp0[k4]; hv[1] = hp1[k4]; hv[2] = hp2[k4]; hv[3] = hp3[k4];
        #pragma unroll
        for (int t = 0; t < 4; t++) {
            int kk = k4*4 + t;
            unsigned long long hb[4];
            #pragma unroll
            for (int r = 0; r < 4; r++) {
                float f = (t == 0) ? hv[r].x : (t == 1) ? hv[r].y
                        : (t == 2) ? hv[r].z : hv[r].w;
                hb[r] = pack2(f, f);
            }
            #pragma unroll
            for (int m = 0; m < 3; m++) {
                ulonglong2 w = *(const ulonglong2*)&Ws[m][kk*HID + cg];
                #pragma unroll
                for (int r = 0; r < 4; r++) {
                    acc[m][r][0] = fma2(hb[r], w.x, acc[m][r][0]);
                    acc[m][r][1] = fma2(hb[r], w.y, acc[m][r][1]);
                }
            }
        }
    }

    float* outs[3] = {g_q, g_k, g_v};
    #pragma unroll
    for (int m = 0; m < 3; m++) {
        #pragma unroll
        for (int r = 0; r < 4; r++) {
            float o0, o1, o2, o3;
            unpack2(acc[m][r][0], o0, o1);
            unpack2(acc[m][r][1], o2, o3);
            *(float4*)(outs[m] + (rbase+r)*HID + cg) = make_float4(o0, o1, o2, o3);
        }
    }
}

// ---------------- spatial attention (per (b*s, head)) ----------------
// R=4 query rows per key pass (K/V LDS amortized 4x); no-max softmax
// (scores are tiny; masked -> p=0); explicit fallback for empty mask rows.
__global__ __launch_bounds__(256, 2) void spatial_attn_kernel() {
    int bs = blockIdx.x;      // 0..47
    int hh = blockIdx.y;      // 0..7
    __shared__ float4 KsA[NN];   // d0-3
    __shared__ float4 KsB[NN];   // d4-7
    __shared__ float4 VsA[NN];
    __shared__ float4 VsB[NN];
    int tid = threadIdx.x;
    int base = bs*NN*HID;
    const float* kb = g_k + base + hh*DH;
    const float* vb = g_v + base + hh*DH;
    const float* qbp = g_q + base + hh*DH;

    for (int m = tid; m < NN; m += 256) {
        KsA[m] = *(const float4*)(kb + m*HID);
        KsB[m] = *(const float4*)(kb + m*HID + 4);
        VsA[m] = *(const float4*)(vb + m*HID);
        VsB[m] = *(const float4*)(vb + m*HID + 4);
    }
    __syncthreads();

    const ulonglong2* pKA = (const ulonglong2*)KsA;
    const ulonglong2* pKB = (const ulonglong2*)KsB;
    const ulonglong2* pVA = (const ulonglong2*)VsA;
    const ulonglong2* pVB = (const ulonglong2*)VsB;

    int warp = tid >> 5, lane = tid & 31;
    const float scale = 0.35355339059327373f;

    for (int pass = 0; pass < 16; pass++) {
        int nb = pass*32 + warp*4;    // 4 consecutive query rows

        unsigned long long q[4][4];
        #pragma unroll
        for (int r = 0; r < 4; r++) {
            float4 qa = *(const float4*)(qbp + (nb+r)*HID);
            float4 qc = *(const float4*)(qbp + (nb+r)*HID + 4);
            q[r][0] = pack2(qa.x, qa.y);
            q[r][1] = pack2(qa.z, qa.w);
            q[r][2] = pack2(qc.x, qc.y);
            q[r][3] = pack2(qc.z, qc.w);
        }

        unsigned long long acc[4][4];
        float sum[4];
        unsigned mor[4];
        #pragma unroll
        for (int r = 0; r < 4; r++) {
            acc[r][0] = acc[r][1] = acc[r][2] = acc[r][3] = 0ull;
            sum[r] = 0.f; mor[r] = 0u;
        }

        #pragma unroll
        for (int j = 0; j < 16; j++) {
            int m = j*32 + lane;
            ulonglong2 ka  = pKA[m];
            ulonglong2 kb2 = pKB[m];
            ulonglong2 va  = pVA[m];
            ulonglong2 vb2 = pVB[m];
            #pragma unroll
            for (int r = 0; r < 4; r++) {
                unsigned w = g_mask[(nb+r)*16 + j];
                mor[r] |= w;
                unsigned long long d = mul2(q[r][0], ka.x);
                d = fma2(q[r][1], ka.y,  d);
                d = fma2(q[r][2], kb2.x, d);
                d = fma2(q[r][3], kb2.y, d);
                float lo, hi; unpack2(d, lo, hi);
                float s = (lo + hi) * scale;
                float p = ((w >> lane) & 1u) ? __expf(s) : 0.f;
                sum[r] += p;
                unsigned long long pp = pack2(p, p);
                acc[r][0] = fma2(pp, va.x,  acc[r][0]);
                acc[r][1] = fma2(pp, va.y,  acc[r][1]);
                acc[r][2] = fma2(pp, vb2.x, acc[r][2]);
                acc[r][3] = fma2(pp, vb2.y, acc[r][3]);
            }
        }

        // fallback for fully-masked rows: reference softmax -> uniform 1/512
        #pragma unroll
        for (int r = 0; r < 4; r++) {
            if (mor[r] == 0u) {     // warp-uniform (all lanes read same words)
                sum[r] = 512.f;
                #pragma unroll
                for (int j = 0; j < 16; j++) {
                    int m = j*32 + lane;
                    ulonglong2 va  = pVA[m];
                    ulonglong2 vb2 = pVB[m];
                    acc[r][0] = add2(acc[r][0], va.x);
                    acc[r][1] = add2(acc[r][1], va.y);
                    acc[r][2] = add2(acc[r][2], vb2.x);
                    acc[r][3] = add2(acc[r][3], vb2.y);
                }
            }
        }

        #pragma unroll
        for (int r = 0; r < 4; r++) {
            float s = sum[r];
            float a[8];
            unpack2(acc[r][0], a[0], a[1]);
            unpack2(acc[r][1], a[2], a[3]);
            unpack2(acc[r][2], a[4], a[5]);
            unpack2(acc[r][3], a[6], a[7]);
            #pragma unroll
            for (int o = 16; o; o >>= 1) {
                s += __shfl_xor_sync(0xffffffffu, s, o);
                #pragma unroll
                for (int d = 0; d < 8; d++)
                    a[d] += __shfl_xor_sync(0xffffffffu, a[d], o);
            }
            if (lane == 0) {
                float inv = 1.f / s;
                float* op = g_h + base + (nb+r)*HID + hh*DH;
                *(float4*)op       = make_float4(a[0]*inv, a[1]*inv, a[2]*inv, a[3]*inv);
                *(float4*)(op + 4) = make_float4(a[4]*inv, a[5]*inv, a[6]*inv, a[7]*inv);
            }
        }
    }
}

// ---------------- temporal attention (per (b, n)) ----------------
__global__ __launch_bounds__(96) void temporal_attn_kernel() {
    int b = blockIdx.x >> 9;       // /512
    int n = blockIdx.x & 511;
    __shared__ float qs[SS][HID];
    __shared__ float ks[SS][HID];
    __shared__ float vs[SS][HID];
    int tid = threadIdx.x;   // 96

    for (int i = tid; i < SS*HID; i += 96) {
        int s = i >> 6, d = i & 63;
        int g = ((b*SS + s)*NN + n)*HID + d;
        qs[s][d] = g_q[g];
        ks[s][d] = g_k[g];
        vs[s][d] = g_v[g];
    }
    __syncthreads();

    int h = tid / SS;
    int s = tid % SS;
    const float scale = 0.35355339059327373f;

    float q8[8];
    #pragma unroll
    for (int d = 0; d < 8; d++) q8[d] = qs[s][h*8 + d];

    float sc[SS];
    float mx = -3e38f;
    #pragma unroll
    for (int t = 0; t < SS; t++) {
        float v = 0.f;
        #pragma unroll
        for (int d = 0; d < 8; d++) v += q8[d]*ks[t][h*8 + d];
        v *= scale;
        sc[t] = v;
        mx = fmaxf(mx, v);
    }
    float sum = 0.f;
    #pragma unroll
    for (int t = 0; t < SS; t++) { sc[t] = __expf(sc[t] - mx); sum += sc[t]; }
    float inv = 1.f / sum;

    float o[8] = {0.f,0.f,0.f,0.f,0.f,0.f,0.f,0.f};
    #pragma unroll
    for (int t = 0; t < SS; t++) {
        float p = sc[t];
        #pragma unroll
        for (int d = 0; d < 8; d++) o[d] += p*vs[t][h*8 + d];
    }
    int g = ((b*SS + s)*NN + n)*HID + h*8;
    #pragma unroll
    for (int d = 0; d < 8; d++) g_h[g + d] = o[d]*inv;
}

// ---------------- output projection: out = h[:, -1] @ Wout^T + bout ----------
__global__ void out_proj_kernel(const float* __restrict__ Wout,
                                const float* __restrict__ bout,
                                float* __restrict__ out) {
    int i = blockIdx.x*256 + threadIdx.x;   // B*N*COUT = 6144
    if (i >= BB*NN*COUT) return;
    int c = i % COUT;
    int bn = i / COUT;
    int b = bn / NN, n = bn % NN;
    const float* hr = g_h + ((b*SS + (SS-1))*NN + n)*HID;
    float a = bout[c];
    #pragma unroll 8
    for (int k = 0; k < HID; k++) a += hr[k]*Wout[c*HID + k];
    out[i] = a;
}

// ---------------- launch ----------------
extern "C" void kernel_launch(void* const* d_in, const int* in_sizes, int n_in,
                              void* d_out, int out_size) {
    const float* x    = (const float*)d_in[0];
    const int*   ei   = (const int*)  d_in[1];
    const float* Win  = (const float*)d_in[2];
    const float* bin  = (const float*)d_in[3];
    const float* Wqs  = (const float*)d_in[4];
    const float* bqs  = (const float*)d_in[5];
    const float* Wks  = (const float*)d_in[6];
    const float* bks  = (const float*)d_in[7];
    const float* Wvs  = (const float*)d_in[8];
    const float* bvs  = (const float*)d_in[9];
    const float* Wqt  = (const float*)d_in[10];
    const float* bqt  = (const float*)d_in[11];
    const float* Wkt  = (const float*)d_in[12];
    const float* bkt  = (const float*)d_in[13];
    const float* Wvt  = (const float*)d_in[14];
    const float* bvt  = (const float*)d_in[15];
    const float* Wout = (const float*)d_in[16];
    const float* bout = (const float*)d_in[17];
    float* out = (float*)d_out;

    zero_mask_kernel<<<(NN*16 + 255)/256, 256>>>();
    scatter_mask_kernel<<<(NE + 255)/256, 256>>>(ei);
    input_proj_kernel<<<(BSN*HID + 255)/256, 256>>>(x, Win, bin);

    for (int l = 0; l < LAYERS; l++) {
        const int wo = l*HID*HID, bo = l*HID;
        // spatial
        qkv_proj_kernel<<<BSN/64, 256>>>(Wqs + wo, bqs + bo,
                                         Wks + wo, bks + bo,
                                         Wvs + wo, bvs + bo);
        spatial_attn_kernel<<<dim3(BB*SS, HEADS), 256>>>();
        // temporal
        qkv_proj_kernel<<<BSN/64, 256>>>(Wqt + wo, bqt + bo,
                                         Wkt + wo, bkt + bo,
                                         Wvt + wo, bvt + bo);
        temporal_attn_kernel<<<BB*NN, 96>>>();
    }

    out_proj_kernel<<<(BB*NN*COUT + 255)/256, 256>>>(Wout, bout, out);
}

// round 15
// speedup vs baseline: 1.0028x; 1.0028x over previous
#include <cuda_runtime.h>

#define BB 4
#define SS 12
#define NN 512
#define CIN 3
#define COUT 3
#define HID 64
#define HEADS 8
#define DH 8
#define LAYERS 2
#define NE 8192
#define BSN (BB*SS*NN)

// ---------------- f32x2 packed-FMA helpers (sm_100+: ptxas won't auto-fuse) --
__device__ __forceinline__ unsigned long long pack2(float lo, float hi) {
    unsigned long long r;
    asm("mov.b64 %0, {%1, %2};" : "=l"(r) : "f"(lo), "f"(hi));
    return r;
}
__device__ __forceinline__ void unpack2(unsigned long long v, float& lo, float& hi) {
    asm("mov.b64 {%0, %1}, %2;" : "=f"(lo), "=f"(hi) : "l"(v));
}
__device__ __forceinline__ unsigned long long fma2(unsigned long long a,
                                                   unsigned long long b,
                                                   unsigned long long c) {
    unsigned long long d;
    asm("fma.rn.f32x2 %0, %1, %2, %3;" : "=l"(d) : "l"(a), "l"(b), "l"(c));
    return d;
}
__device__ __forceinline__ unsigned long long mul2(unsigned long long a,
                                                   unsigned long long b) {
    unsigned long long d;
    asm("mul.rn.f32x2 %0, %1, %2;" : "=l"(d) : "l"(a), "l"(b));
    return d;
}
__device__ __forceinline__ unsigned long long add2(unsigned long long a,
                                                   unsigned long long b) {
    unsigned long long d;
    asm("add.rn.f32x2 %0, %1, %2;" : "=l"(d) : "l"(a), "l"(b));
    return d;
}

// ---------------- scratch (device globals: no allocs allowed) ----------------
__device__ float g_h[BSN*HID];
__device__ float g_q[BSN*HID];
__device__ float g_k[BSN*HID];
__device__ float g_v[BSN*HID];
__device__ unsigned g_mask[NN*16];   // 512 rows x 512-bit mask

// ---------------- mask build ----------------
__global__ void zero_mask_kernel() {
    int i = blockIdx.x*256 + threadIdx.x;
    if (i < NN*16) g_mask[i] = 0u;
}

__global__ void scatter_mask_kernel(const int* __restrict__ ei) {
    int e = blockIdx.x*256 + threadIdx.x;
    if (e < NE) {
        int r = ei[e];
        int c = ei[NE + e];
        atomicOr(&g_mask[r*16 + (c >> 5)], 1u << (c & 31));
    }
}

// ---------------- input projection: h = x @ Win^T + b_in ----------------
__global__ void input_proj_kernel(const float* __restrict__ x,
                                  const float* __restrict__ Win,
                                  const float* __restrict__ bin) {
    int i = blockIdx.x*256 + threadIdx.x;
    if (i >= BSN*HID) return;
    int row = i >> 6, c = i & 63;
    const float* xr = x + row*CIN;
    float a = bin[c];
    a += xr[0]*Win[c*CIN+0];
    a += xr[1]*Win[c*CIN+1];
    a += xr[2]*Win[c*CIN+2];
    g_h[i] = a;
}

// ---------------- fused QKV projection (reads g_h, writes g_q/g_k/g_v) -------
// Block: 64 rows. Thread: 4 rows x 4 cols x 3 matrices, f32x2 accumulators.
__global__ __launch_bounds__(256, 3) void qkv_proj_kernel(
        const float* __restrict__ Wq, const float* __restrict__ bq,
        const float* __restrict__ Wk, const float* __restrict__ bk,
        const float* __restrict__ Wv, const float* __restrict__ bv) {
    __shared__ float Ws[3][HID*HID];      // 48 KB, stored transposed [k][c]
    int tid = threadIdx.x;
    for (int i = tid; i < HID*HID; i += 256) {
        int c = i >> 6, k = i & 63;
        Ws[0][k*HID + c] = Wq[i];
        Ws[1][k*HID + c] = Wk[i];
        Ws[2][k*HID + c] = Wv[i];
    }
    __syncthreads();

    int cg = (tid & 15) * 4;
    int rbase = blockIdx.x*64 + (tid >> 4)*4;

    // acc[mat][row][colpair] as f32x2
    unsigned long long acc[3][4][2];
    #pragma unroll
    for (int m = 0; m < 3; m++) {
        const float* bias = (m == 0) ? bq : (m == 1) ? bk : bv;
        unsigned long long b01 = pack2(bias[cg+0], bias[cg+1]);
        unsigned long long b23 = pack2(bias[cg+2], bias[cg+3]);
        #pragma unroll
        for (int r = 0; r < 4; r++) { acc[m][r][0] = b01; acc[m][r][1] = b23; }
    }

    const float4* hp0 = (const float4*)(g_h + (rbase+0)*HID);
    const float4* hp1 = (const float4*)(g_h + (rbase+1)*HID);
    const float4* hp2 = (const float4*)(g_h + (rbase+2)*HID);
    const float4* hp3 = (const float4*)(g_h + (rbase+3)*HID);

    #pragma unroll 4
    for (int k4 = 0; k4 < 16; k4++) {
        float4 hv[4];
        hv[0] = hp0[k4]; hv[1] = hp1[k4]; hv[2] = hp2[k4]; hv[3] = hp3[k4];
        #pragma unroll
        for (int t = 0; t < 4; t++) {
            int kk = k4*4 + t;
            unsigned long long hb[4];
            #pragma unroll
            for (int r = 0; r < 4; r++) {
                float f = (t == 0) ? hv[r].x : (t == 1) ? hv[r].y
                        : (t == 2) ? hv[r].z : hv[r].w;
                hb[r] = pack2(f, f);
            }
            #pragma unroll
            for (int m = 0; m < 3; m++) {
                ulonglong2 w = *(const ulonglong2*)&Ws[m][kk*HID + cg];
                #pragma unroll
                for (int r = 0; r < 4; r++) {
                    acc[m][r][0] = fma2(hb[r], w.x, acc[m][r][0]);
                    acc[m][r][1] = fma2(hb[r], w.y, acc[m][r][1]);
                }
            }
        }
    }

    float* outs[3] = {g_q, g_k, g_v};
    #pragma unroll
    for (int m = 0; m < 3; m++) {
        #pragma unroll
        for (int r = 0; r < 4; r++) {
            float o0, o1, o2, o3;
            unpack2(acc[m][r][0], o0, o1);
            unpack2(acc[m][r][1], o2, o3);
            *(float4*)(outs[m] + (rbase+r)*HID + cg) = make_float4(o0, o1, o2, o3);
        }
    }
}

// ---------------- spatial attention (per (b*s, head)) ----------------
// R=4 query rows per key pass (K/V LDS amortized 4x); no-max softmax
// (scores are tiny; masked -> p=0); explicit fallback for empty mask rows.
__global__ __launch_bounds__(256, 2) void spatial_attn_kernel() {
    int bs = blockIdx.x;      // 0..47
    int hh = blockIdx.y;      // 0..7
    __shared__ float4 KsA[NN];   // d0-3
    __shared__ float4 KsB[NN];   // d4-7
    __shared__ float4 VsA[NN];
    __shared__ float4 VsB[NN];
    int tid = threadIdx.x;
    int base = bs*NN*HID;
    const float* kb = g_k + base + hh*DH;
    const float* vb = g_v + base + hh*DH;
    const float* qbp = g_q + base + hh*DH;

    for (int m = tid; m < NN; m += 256) {
        KsA[m] = *(const float4*)(kb + m*HID);
        KsB[m] = *(const float4*)(kb + m*HID + 4);
        VsA[m] = *(const float4*)(vb + m*HID);
        VsB[m] = *(const float4*)(vb + m*HID + 4);
    }
    __syncthreads();

    const ulonglong2* pKA = (const ulonglong2*)KsA;
    const ulonglong2* pKB = (const ulonglong2*)KsB;
    const ulonglong2* pVA = (const ulonglong2*)VsA;
    const ulonglong2* pVB = (const ulonglong2*)VsB;

    int warp = tid >> 5, lane = tid & 31;
    const float scale = 0.35355339059327373f;

    for (int pass = 0; pass < 16; pass++) {
        int nb = pass*32 + warp*4;    // 4 consecutive query rows

        unsigned long long q[4][4];
        #pragma unroll
        for (int r = 0; r < 4; r++) {
            float4 qa = *(const float4*)(qbp + (nb+r)*HID);
            float4 qc = *(const float4*)(qbp + (nb+r)*HID + 4);
            q[r][0] = pack2(qa.x, qa.y);
            q[r][1] = pack2(qa.z, qa.w);
            q[r][2] = pack2(qc.x, qc.y);
            q[r][3] = pack2(qc.z, qc.w);
        }

        unsigned long long acc[4][4];
        float sum[4];
        unsigned mor[4];
        #pragma unroll
        for (int r = 0; r < 4; r++) {
            acc[r][0] = acc[r][1] = acc[r][2] = acc[r][3] = 0ull;
            sum[r] = 0.f; mor[r] = 0u;
        }

        #pragma unroll
        for (int j = 0; j < 16; j++) {
            int m = j*32 + lane;
            ulonglong2 ka  = pKA[m];
            ulonglong2 kb2 = pKB[m];
            ulonglong2 va  = pVA[m];
            ulonglong2 vb2 = pVB[m];
            #pragma unroll
            for (int r = 0; r < 4; r++) {
                unsigned w = g_mask[(nb+r)*16 + j];
                mor[r] |= w;
                unsigned long long d = mul2(q[r][0], ka.x);
                d = fma2(q[r][1], ka.y,  d);
                d = fma2(q[r][2], kb2.x, d);
                d = fma2(q[r][3], kb2.y, d);
                float lo, hi; unpack2(d, lo, hi);
                float s = (lo + hi) * scale;
                float p = ((w >> lane) & 1u) ? __expf(s) : 0.f;
                sum[r] += p;
                unsigned long long pp = pack2(p, p);
                acc[r][0] = fma2(pp, va.x,  acc[r][0]);
                acc[r][1] = fma2(pp, va.y,  acc[r][1]);
                acc[r][2] = fma2(pp, vb2.x, acc[r][2]);
                acc[r][3] = fma2(pp, vb2.y, acc[r][3]);
            }
        }

        // fallback for fully-masked rows: reference softmax -> uniform 1/512
        #pragma unroll
        for (int r = 0; r < 4; r++) {
            if (mor[r] == 0u) {     // warp-uniform (all lanes read same words)
                sum[r] = 512.f;
                #pragma unroll
                for (int j = 0; j < 16; j++) {
                    int m = j*32 + lane;
                    ulonglong2 va  = pVA[m];
                    ulonglong2 vb2 = pVB[m];
                    acc[r][0] = add2(acc[r][0], va.x);
                    acc[r][1] = add2(acc[r][1], va.y);
                    acc[r][2] = add2(acc[r][2], vb2.x);
                    acc[r][3] = add2(acc[r][3], vb2.y);
                }
            }
        }

        #pragma unroll
        for (int r = 0; r < 4; r++) {
            float s = sum[r];
            float a[8];
            unpack2(acc[r][0], a[0], a[1]);
            unpack2(acc[r][1], a[2], a[3]);
            unpack2(acc[r][2], a[4], a[5]);
            unpack2(acc[r][3], a[6], a[7]);
            #pragma unroll
            for (int o = 16; o; o >>= 1) {
                s += __shfl_xor_sync(0xffffffffu, s, o);
                #pragma unroll
                for (int d = 0; d < 8; d++)
                    a[d] += __shfl_xor_sync(0xffffffffu, a[d], o);
            }
            if (lane == 0) {
                float inv = 1.f / s;
                float* op = g_h + base + (nb+r)*HID + hh*DH;
                *(float4*)op       = make_float4(a[0]*inv, a[1]*inv, a[2]*inv, a[3]*inv);
                *(float4*)(op + 4) = make_float4(a[4]*inv, a[5]*inv, a[6]*inv, a[7]*inv);
            }
        }
    }
}

// ---------------- temporal attention (per (b, n)) ----------------
__global__ __launch_bounds__(96) void temporal_attn_kernel() {
    int b = blockIdx.x >> 9;       // /512
    int n = blockIdx.x & 511;
    __shared__ float qs[SS][HID];
    __shared__ float ks[SS][HID];
    __shared__ float vs[SS][HID];
    int tid = threadIdx.x;   // 96

    for (int i = tid; i < SS*HID; i += 96) {
        int s = i >> 6, d = i & 63;
        int g = ((b*SS + s)*NN + n)*HID + d;
        qs[s][d] = g_q[g];
        ks[s][d] = g_k[g];
        vs[s][d] = g_v[g];
    }
    __syncthreads();

    int h = tid / SS;
    int s = tid % SS;
    const float scale = 0.35355339059327373f;

    float q8[8];
    #pragma unroll
    for (int d = 0; d < 8; d++) q8[d] = qs[s][h*8 + d];

    float sc[SS];
    float mx = -3e38f;
    #pragma unroll
    for (int t = 0; t < SS; t++) {
        float v = 0.f;
        #pragma unroll
        for (int d = 0; d < 8; d++) v += q8[d]*ks[t][h*8 + d];
        v *= scale;
        sc[t] = v;
        mx = fmaxf(mx, v);
    }
    float sum = 0.f;
    #pragma unroll
    for (int t = 0; t < SS; t++) { sc[t] = __expf(sc[t] - mx); sum += sc[t]; }
    float inv = 1.f / sum;

    float o[8] = {0.f,0.f,0.f,0.f,0.f,0.f,0.f,0.f};
    #pragma unroll
    for (int t = 0; t < SS; t++) {
        float p = sc[t];
        #pragma unroll
        for (int d = 0; d < 8; d++) o[d] += p*vs[t][h*8 + d];
    }
    int g = ((b*SS + s)*NN + n)*HID + h*8;
    #pragma unroll
    for (int d = 0; d < 8; d++) g_h[g + d] = o[d]*inv;
}

// ---------------- output projection: out = h[:, -1] @ Wout^T + bout ----------
__global__ void out_proj_kernel(const float* __restrict__ Wout,
                                const float* __restrict__ bout,
                                float* __restrict__ out) {
    int i = blockIdx.x*256 + threadIdx.x;   // B*N*COUT = 6144
    if (i >= BB*NN*COUT) return;
    int c = i % COUT;
    int bn = i / COUT;
    int b = bn / NN, n = bn % NN;
    const float* hr = g_h + ((b*SS + (SS-1))*NN + n)*HID;
    float a = bout[c];
    #pragma unroll 8
    for (int k = 0; k < HID; k++) a += hr[k]*Wout[c*HID + k];
    out[i] = a;
}

// ---------------- launch ----------------
extern "C" void kernel_launch(void* const* d_in, const int* in_sizes, int n_in,
                              void* d_out, int out_size) {
    const float* x    = (const float*)d_in[0];
    const int*   ei   = (const int*)  d_in[1];
    const float* Win  = (const float*)d_in[2];
    const float* bin  = (const float*)d_in[3];
    const float* Wqs  = (const float*)d_in[4];
    const float* bqs  = (const float*)d_in[5];
    const float* Wks  = (const float*)d_in[6];
    const float* bks  = (const float*)d_in[7];
    const float* Wvs  = (const float*)d_in[8];
    const float* bvs  = (const float*)d_in[9];
    const float* Wqt  = (const float*)d_in[10];
    const float* bqt  = (const float*)d_in[11];
    const float* Wkt  = (const float*)d_in[12];
    const float* bkt  = (const float*)d_in[13];
    const float* Wvt  = (const float*)d_in[14];
    const float* bvt  = (const float*)d_in[15];
    const float* Wout = (const float*)d_in[16];
    const float* bout = (const float*)d_in[17];
    float* out = (float*)d_out;

    zero_mask_kernel<<<(NN*16 + 255)/256, 256>>>();
    scatter_mask_kernel<<<(NE + 255)/256, 256>>>(ei);
    input_proj_kernel<<<(BSN*HID + 255)/256, 256>>>(x, Win, bin);

    for (int l = 0; l < LAYERS; l++) {
        const int wo = l*HID*HID, bo = l*HID;
        // spatial
        qkv_proj_kernel<<<BSN/64, 256>>>(Wqs + wo, bqs + bo,
                                         Wks + wo, bks + bo,
                                         Wvs + wo, bvs + bo);
        spatial_attn_kernel<<<dim3(BB*SS, HEADS), 256>>>();
        // temporal
        qkv_proj_kernel<<<BSN/64, 256>>>(Wqt + wo, bqt + bo,
                                         Wkt + wo, bkt + bo,
                                         Wvt + wo, bvt + bo);
        temporal_attn_kernel<<<BB*NN, 96>>>();
    }

    out_proj_kernel<<<(BB*NN*COUT + 255)/256, 256>>>(Wout, bout, out);
}

// round 16
// speedup vs baseline: 1.0066x; 1.0038x over previous
#include <cuda_runtime.h>

#define BB 4
#define SS 12
#define NN 512
#define CIN 3
#define COUT 3
#define HID 64
#define HEADS 8
#define DH 8
#define LAYERS 2
#define NE 8192
#define BSN (BB*SS*NN)

// ---------------- f32x2 packed-FMA helpers (sm_100+: ptxas won't auto-fuse) --
__device__ __forceinline__ unsigned long long pack2(float lo, float hi) {
    unsigned long long r;
    asm("mov.b64 %0, {%1, %2};" : "=l"(r) : "f"(lo), "f"(hi));
    return r;
}
__device__ __forceinline__ void unpack2(unsigned long long v, float& lo, float& hi) {
    asm("mov.b64 {%0, %1}, %2;" : "=f"(lo), "=f"(hi) : "l"(v));
}
__device__ __forceinline__ unsigned long long fma2(unsigned long long a,
                                                   unsigned long long b,
                                                   unsigned long long c) {
    unsigned long long d;
    asm("fma.rn.f32x2 %0, %1, %2, %3;" : "=l"(d) : "l"(a), "l"(b), "l"(c));
    return d;
}
__device__ __forceinline__ unsigned long long mul2(unsigned long long a,
                                                   unsigned long long b) {
    unsigned long long d;
    asm("mul.rn.f32x2 %0, %1, %2;" : "=l"(d) : "l"(a), "l"(b));
    return d;
}
__device__ __forceinline__ unsigned long long add2(unsigned long long a,
                                                   unsigned long long b) {
    unsigned long long d;
    asm("add.rn.f32x2 %0, %1, %2;" : "=l"(d) : "l"(a), "l"(b));
    return d;
}

// ---------------- scratch (device globals: no allocs allowed) ----------------
__device__ float g_h[BSN*HID];
__device__ float g_q[BSN*HID];
__device__ float g_k[BSN*HID];
__device__ float g_v[BSN*HID];
__device__ unsigned g_mask[NN*16];   // 512 rows x 512-bit mask

// ---------------- mask build ----------------
__global__ void zero_mask_kernel() {
    int i = blockIdx.x*256 + threadIdx.x;
    if (i < NN*16) g_mask[i] = 0u;
}

__global__ void scatter_mask_kernel(const int* __restrict__ ei) {
    int e = blockIdx.x*256 + threadIdx.x;
    if (e < NE) {
        int r = ei[e];
        int c = ei[NE + e];
        atomicOr(&g_mask[r*16 + (c >> 5)], 1u << (c & 31));
    }
}

// ---------------- input projection: h = x @ Win^T + b_in ----------------
__global__ void input_proj_kernel(const float* __restrict__ x,
                                  const float* __restrict__ Win,
                                  const float* __restrict__ bin) {
    int i = blockIdx.x*256 + threadIdx.x;
    if (i >= BSN*HID) return;
    int row = i >> 6, c = i & 63;
    const float* xr = x + row*CIN;
    float a = bin[c];
    a += xr[0]*Win[c*CIN+0];
    a += xr[1]*Win[c*CIN+1];
    a += xr[2]*Win[c*CIN+2];
    g_h[i] = a;
}

// ---------------- fused QKV projection (reads g_h, writes g_q/g_k/g_v) -------
// Block: 64 rows. Thread: 4 rows x 4 cols x 3 matrices, f32x2 accumulators.
__global__ __launch_bounds__(256, 3) void qkv_proj_kernel(
        const float* __restrict__ Wq, const float* __restrict__ bq,
        const float* __restrict__ Wk, const float* __restrict__ bk,
        const float* __restrict__ Wv, const float* __restrict__ bv) {
    __shared__ float Ws[3][HID*HID];      // 48 KB, stored transposed [k][c]
    int tid = threadIdx.x;
    for (int i = tid; i < HID*HID; i += 256) {
        int c = i >> 6, k = i & 63;
        Ws[0][k*HID + c] = Wq[i];
        Ws[1][k*HID + c] = Wk[i];
        Ws[2][k*HID + c] = Wv[i];
    }
    __syncthreads();

    int cg = (tid & 15) * 4;
    int rbase = blockIdx.x*64 + (tid >> 4)*4;

    // acc[mat][row][colpair] as f32x2
    unsigned long long acc[3][4][2];
    #pragma unroll
    for (int m = 0; m < 3; m++) {
        const float* bias = (m == 0) ? bq : (m == 1) ? bk : bv;
        unsigned long long b01 = pack2(bias[cg+0], bias[cg+1]);
        unsigned long long b23 = pack2(bias[cg+2], bias[cg+3]);
        #pragma unroll
        for (int r = 0; r < 4; r++) { acc[m][r][0] = b01; acc[m][r][1] = b23; }
    }

    const float4* hp0 = (const float4*)(g_h + (rbase+0)*HID);
    const float4* hp1 = (const float4*)(g_h + (rbase+1)*HID);
    const float4* hp2 = (const float4*)(g_h + (rbase+2)*HID);
    const float4* hp3 = (const float4*)(g_h + (rbase+3)*HID);

    #pragma unroll 4
    for (int k4 = 0; k4 < 16; k4++) {
        float4 hv[4];
        hv[0] = hp0[k4]; hv[1] = hp1[k4]; hv[2] = hp2[k4]; hv[3] = hp3[k4];
        #pragma unroll
        for (int t = 0; t < 4; t++) {
            int kk = k4*4 + t;
            unsigned long long hb[4];
            #pragma unroll
            for (int r = 0; r < 4; r++) {
                float f = (t == 0) ? hv[r].x : (t == 1) ? hv[r].y
                        : (t == 2) ? hv[r].z : hv[r].w;
                hb[r] = pack2(f, f);
            }
            #pragma unroll
            for (int m = 0; m < 3; m++) {
                ulonglong2 w = *(const ulonglong2*)&Ws[m][kk*HID + cg];
                #pragma unroll
                for (int r = 0; r < 4; r++) {
                    acc[m][r][0] = fma2(hb[r], w.x, acc[m][r][0]);
                    acc[m][r][1] = fma2(hb[r], w.y, acc[m][r][1]);
                }
            }
        }
    }

    float* outs[3] = {g_q, g_k, g_v};
    #pragma unroll
    for (int m = 0; m < 3; m++) {
        #pragma unroll
        for (int r = 0; r < 4; r++) {
            float o0, o1, o2, o3;
            unpack2(acc[m][r][0], o0, o1);
            unpack2(acc[m][r][1], o2, o3);
            *(float4*)(outs[m] + (rbase+r)*HID + cg) = make_float4(o0, o1, o2, o3);
        }
    }
}

// ---------------- spatial attention (per (b*s, head)) ----------------
// R=4 query rows per key pass (K/V LDS amortized 4x); no-max softmax
// (scores are tiny; masked -> p=0); explicit fallback for empty mask rows.
__global__ __launch_bounds__(256, 2) void spatial_attn_kernel() {
    int bs = blockIdx.x;      // 0..47
    int hh = blockIdx.y;      // 0..7
    __shared__ float4 KsA[NN];   // d0-3
    __shared__ float4 KsB[NN];   // d4-7
    __shared__ float4 VsA[NN];
    __shared__ float4 VsB[NN];
    int tid = threadIdx.x;
    int base = bs*NN*HID;
    const float* kb = g_k + base + hh*DH;
    const float* vb = g_v + base + hh*DH;
    const float* qbp = g_q + base + hh*DH;

    for (int m = tid; m < NN; m += 256) {
        KsA[m] = *(const float4*)(kb + m*HID);
        KsB[m] = *(const float4*)(kb + m*HID + 4);
        VsA[m] = *(const float4*)(vb + m*HID);
        VsB[m] = *(const float4*)(vb + m*HID + 4);
    }
    __syncthreads();

    const ulonglong2* pKA = (const ulonglong2*)KsA;
    const ulonglong2* pKB = (const ulonglong2*)KsB;
    const ulonglong2* pVA = (const ulonglong2*)VsA;
    const ulonglong2* pVB = (const ulonglong2*)VsB;

    int warp = tid >> 5, lane = tid & 31;
    const float scale = 0.35355339059327373f;

    for (int pass = 0; pass < 16; pass++) {
        int nb = pass*32 + warp*4;    // 4 consecutive query rows

        unsigned long long q[4][4];
        #pragma unroll
        for (int r = 0; r < 4; r++) {
            float4 qa = *(const float4*)(qbp + (nb+r)*HID);
            float4 qc = *(const float4*)(qbp + (nb+r)*HID + 4);
            q[r][0] = pack2(qa.x, qa.y);
            q[r][1] = pack2(qa.z, qa.w);
            q[r][2] = pack2(qc.x, qc.y);
            q[r][3] = pack2(qc.z, qc.w);
        }

        unsigned long long acc[4][4];
        float sum[4];
        unsigned mor[4];
        #pragma unroll
        for (int r = 0; r < 4; r++) {
            acc[r][0] = acc[r][1] = acc[r][2] = acc[r][3] = 0ull;
            sum[r] = 0.f; mor[r] = 0u;
        }

        #pragma unroll
        for (int j = 0; j < 16; j++) {
            int m = j*32 + lane;
            ulonglong2 ka  = pKA[m];
            ulonglong2 kb2 = pKB[m];
            ulonglong2 va  = pVA[m];
            ulonglong2 vb2 = pVB[m];
            #pragma unroll
            for (int r = 0; r < 4; r++) {
                unsigned w = g_mask[(nb+r)*16 + j];
                mor[r] |= w;
                unsigned long long d = mul2(q[r][0], ka.x);
                d = fma2(q[r][1], ka.y,  d);
                d = fma2(q[r][2], kb2.x, d);
                d = fma2(q[r][3], kb2.y, d);
                float lo, hi; unpack2(d, lo, hi);
                float s = (lo + hi) * scale;
                float p = ((w >> lane) & 1u) ? __expf(s) : 0.f;
                sum[r] += p;
                unsigned long long pp = pack2(p, p);
                acc[r][0] = fma2(pp, va.x,  acc[r][0]);
                acc[r][1] = fma2(pp, va.y,  acc[r][1]);
                acc[r][2] = fma2(pp, vb2.x, acc[r][2]);
                acc[r][3] = fma2(pp, vb2.y, acc[r][3]);
            }
        }

        // fallback for fully-masked rows: reference softmax -> uniform 1/512
        #pragma unroll
        for (int r = 0; r < 4; r++) {
            if (mor[r] == 0u) {     // warp-uniform (all lanes read same words)
                sum[r] = 512.f;
                #pragma unroll
                for (int j = 0; j < 16; j++) {
                    int m = j*32 + lane;
                    ulonglong2 va  = pVA[m];
                    ulonglong2 vb2 = pVB[m];
                    acc[r][0] = add2(acc[r][0], va.x);
                    acc[r][1] = add2(acc[r][1], va.y);
                    acc[r][2] = add2(acc[r][2], vb2.x);
                    acc[r][3] = add2(acc[r][3], vb2.y);
                }
            }
        }

        #pragma unroll
        for (int r = 0; r < 4; r++) {
            float s = sum[r];
            float a[8];
            unpack2(acc[r][0], a[0], a[1]);
            unpack2(acc[r][1], a[2], a[3]);
            unpack2(acc[r][2], a[4], a[5]);
            unpack2(acc[r][3], a[6], a[7]);
            #pragma unroll
            for (int o = 16; o; o >>= 1) {
                s += __shfl_xor_sync(0xffffffffu, s, o);
                #pragma unroll
                for (int d = 0; d < 8; d++)
                    a[d] += __shfl_xor_sync(0xffffffffu, a[d], o);
            }
            if (lane == 0) {
                float inv = 1.f / s;
                float* op = g_h + base + (nb+r)*HID + hh*DH;
                *(float4*)op       = make_float4(a[0]*inv, a[1]*inv, a[2]*inv, a[3]*inv);
                *(float4*)(op + 4) = make_float4(a[4]*inv, a[5]*inv, a[6]*inv, a[7]*inv);
            }
        }
    }
}

// ---------------- temporal attention (per (b, n)) ----------------
__global__ __launch_bounds__(96) void temporal_attn_kernel() {
    int b = blockIdx.x >> 9;       // /512
    int n = blockIdx.x & 511;
    __shared__ float qs[SS][HID];
    __shared__ float ks[SS][HID];
    __shared__ float vs[SS][HID];
    int tid = threadIdx.x;   // 96

    for (int i = tid; i < SS*HID; i += 96) {
        int s = i >> 6, d = i & 63;
        int g = ((b*SS + s)*NN + n)*HID + d;
        qs[s][d] = g_q[g];
        ks[s][d] = g_k[g];
        vs[s][d] = g_v[g];
    }
    __syncthreads();

    int h = tid / SS;
    int s = tid % SS;
    const float scale = 0.35355339059327373f;

    float q8[8];
    #pragma unroll
    for (int d = 0; d < 8; d++) q8[d] = qs[s][h*8 + d];

    float sc[SS];
    float mx = -3e38f;
    #pragma unroll
    for (int t = 0; t < SS; t++) {
        float v = 0.f;
        #pragma unroll
        for (int d = 0; d < 8; d++) v += q8[d]*ks[t][h*8 + d];
        v *= scale;
        sc[t] = v;
        mx = fmaxf(mx, v);
    }
    float sum = 0.f;
    #pragma unroll
    for (int t = 0; t < SS; t++) { sc[t] = __expf(sc[t] - mx); sum += sc[t]; }
    float inv = 1.f / sum;

    float o[8] = {0.f,0.f,0.f,0.f,0.f,0.f,0.f,0.f};
    #pragma unroll
    for (int t = 0; t < SS; t++) {
        float p = sc[t];
        #pragma unroll
        for (int d = 0; d < 8; d++) o[d] += p*vs[t][h*8 + d];
    }
    int g = ((b*SS + s)*NN + n)*HID + h*8;
    #pragma unroll
    for (int d = 0; d < 8; d++) g_h[g + d] = o[d]*inv;
}

// ---------------- output projection: out = h[:, -1] @ Wout^T + bout ----------
__global__ void out_proj_kernel(const float* __restrict__ Wout,
                                const float* __restrict__ bout,
                                float* __restrict__ out) {
    int i = blockIdx.x*256 + threadIdx.x;   // B*N*COUT = 6144
    if (i >= BB*NN*COUT) return;
    int c = i % COUT;
    int bn = i / COUT;
    int b = bn / NN, n = bn % NN;
    const float* hr = g_h + ((b*SS + (SS-1))*NN + n)*HID;
    float a = bout[c];
    #pragma unroll 8
    for (int k = 0; k < HID; k++) a += hr[k]*Wout[c*HID + k];
    out[i] = a;
}

// ---------------- launch ----------------
extern "C" void kernel_launch(void* const* d_in, const int* in_sizes, int n_in,
                              void* d_out, int out_size) {
    const float* x    = (const float*)d_in[0];
    const int*   ei   = (const int*)  d_in[1];
    const float* Win  = (const float*)d_in[2];
    const float* bin  = (const float*)d_in[3];
    const float* Wqs  = (const float*)d_in[4];
    const float* bqs  = (const float*)d_in[5];
    const float* Wks  = (const float*)d_in[6];
    const float* bks  = (const float*)d_in[7];
    const float* Wvs  = (const float*)d_in[8];
    const float* bvs  = (const float*)d_in[9];
    const float* Wqt  = (const float*)d_in[10];
    const float* bqt  = (const float*)d_in[11];
    const float* Wkt  = (const float*)d_in[12];
    const float* bkt  = (const float*)d_in[13];
    const float* Wvt  = (const float*)d_in[14];
    const float* bvt  = (const float*)d_in[15];
    const float* Wout = (const float*)d_in[16];
    const float* bout = (const float*)d_in[17];
    float* out = (float*)d_out;

    zero_mask_kernel<<<(NN*16 + 255)/256, 256>>>();
    scatter_mask_kernel<<<(NE + 255)/256, 256>>>(ei);
    input_proj_kernel<<<(BSN*HID + 255)/256, 256>>>(x, Win, bin);

    for (int l = 0; l < LAYERS; l++) {
        const int wo = l*HID*HID, bo = l*HID;
        // spatial
        qkv_proj_kernel<<<BSN/64, 256>>>(Wqs + wo, bqs + bo,
                                         Wks + wo, bks + bo,
                                         Wvs + wo, bvs + bo);
        spatial_attn_kernel<<<dim3(BB*SS, HEADS), 256>>>();
        // temporal
        qkv_proj_kernel<<<BSN/64, 256>>>(Wqt + wo, bqt + bo,
                                         Wkt + wo, bkt + bo,
                                         Wvt + wo, bvt + bo);
        temporal_attn_kernel<<<BB*NN, 96>>>();
    }

    out_proj_kernel<<<(BB*NN*COUT + 255)/256, 256>>>(Wout, bout, out);
}